// round 1
// baseline (speedup 1.0000x reference)
#include <cuda_runtime.h>
#include <math.h>

// Problem constants (BEVNet_26491358282245): x[2,160,160,128], qkv_w[384,128],
// proj_w[128,128], proj_b[128]. DILS=(1,2), KS=3, NH=8 -> hd=16, 4 heads/dilation.
#define B_ 2
#define H_ 160
#define W_ 160
#define C_ 128
#define NPIX (B_*H_*W_)   /* 51200 */

// Scratch (module-load allocated; no runtime alloc).
__device__ float g_qkv[(size_t)NPIX * 384];   // [pix, 3*C]  (q|k|v, each dil*64+head*16+c)
__device__ float g_att[(size_t)NPIX * 128];   // [pix, C] attention output (concat layout)

// ---------------------------------------------------------------------------
// Tiled fp32 GEMM:  C[M,N] = A[M,K] * Bw[N,K]^T (+ bias[N])
// BM=BN=128, BK=8, 256 threads, 8x8 per thread.
// ---------------------------------------------------------------------------
#define BM 128
#define BN 128
#define BK 8
#define TM 8
#define TN 8

__global__ __launch_bounds__(256) void sgemm_nt(
    const float* __restrict__ A,
    const float* __restrict__ Bw,
    const float* __restrict__ bias,
    float* __restrict__ C,
    int M, int N, int K)
{
    __shared__ __align__(16) float As[BK][BM];
    __shared__ __align__(16) float Bs[BK][BN];

    const int bm  = blockIdx.x * BM;
    const int bn  = blockIdx.y * BN;
    const int tid = threadIdx.x;
    const int tr  = tid >> 4;        // 0..15
    const int tc  = tid & 15;        // 0..15

    const int lrow = tid >> 1;       // 0..127
    const int lcol = (tid & 1) << 2; // 0 or 4

    const float* Ap = A  + (size_t)(bm + lrow) * K + lcol;
    const float* Bp = Bw + (size_t)(bn + lrow) * K + lcol;

    float acc[TM][TN];
    #pragma unroll
    for (int i = 0; i < TM; i++)
        #pragma unroll
        for (int j = 0; j < TN; j++) acc[i][j] = 0.f;

    for (int k0 = 0; k0 < K; k0 += BK) {
        float4 a4 = *(const float4*)(Ap + k0);
        float4 b4 = *(const float4*)(Bp + k0);
        __syncthreads();
        As[lcol+0][lrow] = a4.x; As[lcol+1][lrow] = a4.y;
        As[lcol+2][lrow] = a4.z; As[lcol+3][lrow] = a4.w;
        Bs[lcol+0][lrow] = b4.x; Bs[lcol+1][lrow] = b4.y;
        Bs[lcol+2][lrow] = b4.z; Bs[lcol+3][lrow] = b4.w;
        __syncthreads();
        #pragma unroll
        for (int k = 0; k < BK; k++) {
            float4 a0 = *(const float4*)&As[k][tr*TM];
            float4 a1 = *(const float4*)&As[k][tr*TM + 4];
            float4 b0 = *(const float4*)&Bs[k][tc*TN];
            float4 b1 = *(const float4*)&Bs[k][tc*TN + 4];
            float ra[8] = {a0.x,a0.y,a0.z,a0.w,a1.x,a1.y,a1.z,a1.w};
            float rb[8] = {b0.x,b0.y,b0.z,b0.w,b1.x,b1.y,b1.z,b1.w};
            #pragma unroll
            for (int i = 0; i < TM; i++)
                #pragma unroll
                for (int j = 0; j < TN; j++)
                    acc[i][j] = fmaf(ra[i], rb[j], acc[i][j]);
        }
    }

    float bb[TN];
    #pragma unroll
    for (int j = 0; j < TN; j++) bb[j] = bias ? bias[bn + tc*TN + j] : 0.f;

    #pragma unroll
    for (int i = 0; i < TM; i++) {
        float* cp = C + (size_t)(bm + tr*TM + i) * N + bn + tc*TN;
        float4 v0, v1;
        v0.x = acc[i][0] + bb[0]; v0.y = acc[i][1] + bb[1];
        v0.z = acc[i][2] + bb[2]; v0.w = acc[i][3] + bb[3];
        v1.x = acc[i][4] + bb[4]; v1.y = acc[i][5] + bb[5];
        v1.z = acc[i][6] + bb[6]; v1.w = acc[i][7] + bb[7];
        *(float4*)cp       = v0;
        *(float4*)(cp + 4) = v1;
    }
}

// ---------------------------------------------------------------------------
// Dilated 3x3 neighborhood attention.
// One thread per (pixel, dilation, head): hd=16.
// Zero-pad semantics: OOB neighbor -> score 0 (participates in softmax),
// v contribution 0.
// ---------------------------------------------------------------------------
__global__ __launch_bounds__(256) void attn_kernel(
    const float* __restrict__ qkv, float* __restrict__ att)
{
    const int t  = blockIdx.x * 256 + threadIdx.x;   // 0 .. NPIX*8-1
    const int m  = t >> 3;
    const int j  = t & 7;
    const int di = j >> 2;        // dilation index: 0 -> r=1, 1 -> r=2
    const int r  = 1 + di;
    const int hh = j & 3;         // head within dilation
    const int x  = m % W_;
    const int y  = (m / W_) % H_;

    const size_t base = (size_t)m * 384 + di*64 + hh*16;
    const float4* qp = (const float4*)(qkv + base);
    const float4 q0 = qp[0], q1 = qp[1], q2 = qp[2], q3 = qp[3];

    float s[9];
    bool  inb[9];
    int   noff[9];
    #pragma unroll
    for (int kk = 0; kk < 9; kk++) {
        const int dy = (kk/3 - 1) * r;
        const int dx = (kk%3 - 1) * r;
        const int ny = y + dy, nx = x + dx;
        const bool ok = (ny >= 0) & (ny < H_) & (nx >= 0) & (nx < W_);
        inb[kk]  = ok;
        noff[kk] = dy*W_ + dx;
        float sc = 0.f;
        if (ok) {
            const float4* kp = (const float4*)(qkv + base + (ptrdiff_t)noff[kk]*384 + 128);
            const float4 k0 = kp[0], k1 = kp[1], k2 = kp[2], k3 = kp[3];
            sc = q0.x*k0.x + q0.y*k0.y + q0.z*k0.z + q0.w*k0.w
               + q1.x*k1.x + q1.y*k1.y + q1.z*k1.z + q1.w*k1.w
               + q2.x*k2.x + q2.y*k2.y + q2.z*k2.z + q2.w*k2.w
               + q3.x*k3.x + q3.y*k3.y + q3.z*k3.z + q3.w*k3.w;
            sc *= 0.25f;  // hd^-0.5, hd=16
        }
        s[kk] = sc;
    }

    float mx = s[0];
    #pragma unroll
    for (int kk = 1; kk < 9; kk++) mx = fmaxf(mx, s[kk]);
    float sum = 0.f;
    #pragma unroll
    for (int kk = 0; kk < 9; kk++) { s[kk] = expf(s[kk] - mx); sum += s[kk]; }
    const float inv = 1.f / sum;

    float4 o0 = {0,0,0,0}, o1 = {0,0,0,0}, o2 = {0,0,0,0}, o3 = {0,0,0,0};
    #pragma unroll
    for (int kk = 0; kk < 9; kk++) {
        if (inb[kk]) {
            const float w = s[kk] * inv;
            const float4* vp = (const float4*)(qkv + base + (ptrdiff_t)noff[kk]*384 + 256);
            const float4 v0 = vp[0], v1 = vp[1], v2 = vp[2], v3 = vp[3];
            o0.x += w*v0.x; o0.y += w*v0.y; o0.z += w*v0.z; o0.w += w*v0.w;
            o1.x += w*v1.x; o1.y += w*v1.y; o1.z += w*v1.z; o1.w += w*v1.w;
            o2.x += w*v2.x; o2.y += w*v2.y; o2.z += w*v2.z; o2.w += w*v2.w;
            o3.x += w*v3.x; o3.y += w*v3.y; o3.z += w*v3.z; o3.w += w*v3.w;
        }
    }

    float4* op = (float4*)(att + (size_t)m * 128 + di*64 + hh*16);
    op[0] = o0; op[1] = o1; op[2] = o2; op[3] = o3;
}

// ---------------------------------------------------------------------------
extern "C" void kernel_launch(void* const* d_in, const int* in_sizes, int n_in,
                              void* d_out, int out_size)
{
    const float* x      = (const float*)d_in[0];
    const float* qkv_w  = (const float*)d_in[1];
    const float* proj_w = (const float*)d_in[2];
    const float* proj_b = (const float*)d_in[3];
    float* out = (float*)d_out;

    float *qkvbuf = nullptr, *attbuf = nullptr;
    cudaGetSymbolAddress((void**)&qkvbuf, g_qkv);
    cudaGetSymbolAddress((void**)&attbuf, g_att);

    // 1) QKV projection: [51200,128] x [384,128]^T -> [51200,384]
    dim3 g1(NPIX / BM, 384 / BN);
    sgemm_nt<<<g1, 256>>>(x, qkv_w, nullptr, qkvbuf, NPIX, 384, C_);

    // 2) Dilated neighborhood attention -> [51200,128]
    attn_kernel<<<(NPIX * 8) / 256, 256>>>(qkvbuf, attbuf);

    // 3) Output projection + bias: [51200,128] x [128,128]^T -> [51200,128]
    dim3 g3(NPIX / BM, 128 / BN);
    sgemm_nt<<<g3, 256>>>(attbuf, proj_w, proj_b, out, NPIX, 128, C_);
}

// round 2
// speedup vs baseline: 1.6895x; 1.6895x over previous
#include <cuda_runtime.h>
#include <math.h>
#include <stdint.h>

// Problem constants (BEVNet_26491358282245): x[2,160,160,128], qkv_w[384,128],
// proj_w[128,128], proj_b[128]. DILS=(1,2), KS=3, NH=8 -> hd=16, 4 heads/dilation.
#define B_ 2
#define H_ 160
#define W_ 160
#define C_ 128
#define NPIX (B_*H_*W_)   /* 51200 */

// Scratch (module-load allocated; no runtime alloc).
__device__ float g_qkv[(size_t)NPIX * 384];   // [pix, 3*C]  (q|k|v, each dil*64+head*16+c)
__device__ float g_att[(size_t)NPIX * 128];   // [pix, C] attention output (concat layout)

// ---------------------------------------------------------------------------
// tf32 tensor-core GEMM:  C[M,N] = A[M,K] * Bw[N,K]^T (+ bias[N])
// BM=BN=128, BK=16, 256 threads (8 warps, 4x2), warp tile 32x64.
// mma.sync.aligned.m16n8k8.row.col.f32.tf32.tf32.f32
// ---------------------------------------------------------------------------
#define SMP 20   // smem row stride (floats) -> conflict-free frag loads

__device__ __forceinline__ uint32_t f2tf32(float f) {
    uint32_t r;
    asm("cvt.rna.tf32.f32 %0, %1;" : "=r"(r) : "f"(f));
    return r;
}

__device__ __forceinline__ void mma_tf32(
    float& c0, float& c1, float& c2, float& c3,
    uint32_t a0, uint32_t a1, uint32_t a2, uint32_t a3,
    uint32_t b0, uint32_t b1)
{
    asm volatile(
        "mma.sync.aligned.m16n8k8.row.col.f32.tf32.tf32.f32 "
        "{%0,%1,%2,%3}, {%4,%5,%6,%7}, {%8,%9}, {%0,%1,%2,%3};"
        : "+f"(c0), "+f"(c1), "+f"(c2), "+f"(c3)
        : "r"(a0), "r"(a1), "r"(a2), "r"(a3), "r"(b0), "r"(b1));
}

__global__ __launch_bounds__(256) void tgemm_nt(
    const float* __restrict__ A,
    const float* __restrict__ Bw,
    const float* __restrict__ bias,
    float* __restrict__ C,
    int M, int N, int K)
{
    __shared__ uint32_t As[128 * SMP];
    __shared__ uint32_t Bs[128 * SMP];

    const int bm   = blockIdx.x * 128;
    const int bn   = blockIdx.y * 128;
    const int tid  = threadIdx.x;
    const int wid  = tid >> 5;
    const int lane = tid & 31;
    const int wm   = (wid & 3) * 32;   // warp m offset (4 warps along M)
    const int wn   = (wid >> 2) * 64;  // warp n offset (2 warps along N)
    const int grp  = lane >> 2;        // 0..7
    const int tg   = lane & 3;         // 0..3

    // Global loader mapping: each thread loads 2 float4 for A and 2 for B.
    const int lr = tid >> 2;           // 0..63
    const int lc = (tid & 3) << 2;     // 0,4,8,12

    const float* Ag = A  + (size_t)(bm + lr) * K + lc;
    const float* Bg = Bw + (size_t)(bn + lr) * K + lc;

    float acc[2][8][4];
    #pragma unroll
    for (int i = 0; i < 2; i++)
        #pragma unroll
        for (int j = 0; j < 8; j++)
            #pragma unroll
            for (int q = 0; q < 4; q++) acc[i][j][q] = 0.f;

    // Prefetch first tile.
    float4 pa0 = *(const float4*)(Ag);
    float4 pa1 = *(const float4*)(Ag + (size_t)64 * K);
    float4 pb0 = *(const float4*)(Bg);
    float4 pb1 = *(const float4*)(Bg + (size_t)64 * K);

    for (int k0 = 0; k0 < K; k0 += 16) {
        // Store prefetched tile into smem (convert to tf32).
        {
            uint32_t* a0p = &As[lr * SMP + lc];
            a0p[0]=f2tf32(pa0.x); a0p[1]=f2tf32(pa0.y); a0p[2]=f2tf32(pa0.z); a0p[3]=f2tf32(pa0.w);
            uint32_t* a1p = &As[(lr + 64) * SMP + lc];
            a1p[0]=f2tf32(pa1.x); a1p[1]=f2tf32(pa1.y); a1p[2]=f2tf32(pa1.z); a1p[3]=f2tf32(pa1.w);
            uint32_t* b0p = &Bs[lr * SMP + lc];
            b0p[0]=f2tf32(pb0.x); b0p[1]=f2tf32(pb0.y); b0p[2]=f2tf32(pb0.z); b0p[3]=f2tf32(pb0.w);
            uint32_t* b1p = &Bs[(lr + 64) * SMP + lc];
            b1p[0]=f2tf32(pb1.x); b1p[1]=f2tf32(pb1.y); b1p[2]=f2tf32(pb1.z); b1p[3]=f2tf32(pb1.w);
        }
        __syncthreads();

        // Prefetch next tile (global only; no smem touch).
        if (k0 + 16 < K) {
            pa0 = *(const float4*)(Ag + k0 + 16);
            pa1 = *(const float4*)(Ag + (size_t)64 * K + k0 + 16);
            pb0 = *(const float4*)(Bg + k0 + 16);
            pb1 = *(const float4*)(Bg + (size_t)64 * K + k0 + 16);
        }

        // Two k-steps of 8 within this BK=16 stage.
        #pragma unroll
        for (int ks = 0; ks < 2; ks++) {
            const int kk = ks * 8;
            uint32_t afr[2][4];
            #pragma unroll
            for (int i = 0; i < 2; i++) {
                const int rb = wm + i * 16;
                afr[i][0] = As[(rb + grp)     * SMP + kk + tg];
                afr[i][1] = As[(rb + grp + 8) * SMP + kk + tg];
                afr[i][2] = As[(rb + grp)     * SMP + kk + tg + 4];
                afr[i][3] = As[(rb + grp + 8) * SMP + kk + tg + 4];
            }
            uint32_t bfr[8][2];
            #pragma unroll
            for (int j = 0; j < 8; j++) {
                const int cb = wn + j * 8;
                bfr[j][0] = Bs[(cb + grp) * SMP + kk + tg];
                bfr[j][1] = Bs[(cb + grp) * SMP + kk + tg + 4];
            }
            #pragma unroll
            for (int i = 0; i < 2; i++)
                #pragma unroll
                for (int j = 0; j < 8; j++)
                    mma_tf32(acc[i][j][0], acc[i][j][1], acc[i][j][2], acc[i][j][3],
                             afr[i][0], afr[i][1], afr[i][2], afr[i][3],
                             bfr[j][0], bfr[j][1]);
        }
        __syncthreads();
    }

    // Epilogue: c0/c1 contiguous along N -> float2 stores (+bias).
    #pragma unroll
    for (int j = 0; j < 8; j++) {
        const int col = bn + wn + j * 8 + 2 * tg;
        float b0 = bias ? bias[col]     : 0.f;
        float b1 = bias ? bias[col + 1] : 0.f;
        #pragma unroll
        for (int i = 0; i < 2; i++) {
            const int r0 = bm + wm + i * 16 + grp;
            float2 v0 = make_float2(acc[i][j][0] + b0, acc[i][j][1] + b1);
            float2 v1 = make_float2(acc[i][j][2] + b0, acc[i][j][3] + b1);
            *(float2*)(C + (size_t)r0 * N + col)       = v0;
            *(float2*)(C + (size_t)(r0 + 8) * N + col) = v1;
        }
    }
}

// ---------------------------------------------------------------------------
// Dilated 3x3 neighborhood attention.
// One thread per (pixel, dilation, head): hd=16.
// Zero-pad semantics: OOB neighbor -> score 0 (participates in softmax),
// v contribution 0.
// ---------------------------------------------------------------------------
__global__ __launch_bounds__(256) void attn_kernel(
    const float* __restrict__ qkv, float* __restrict__ att)
{
    const int t  = blockIdx.x * 256 + threadIdx.x;   // 0 .. NPIX*8-1
    const int m  = t >> 3;
    const int j  = t & 7;
    const int di = j >> 2;        // dilation index: 0 -> r=1, 1 -> r=2
    const int r  = 1 + di;
    const int hh = j & 3;         // head within dilation
    const int x  = m % W_;
    const int y  = (m / W_) % H_;

    const size_t base = (size_t)m * 384 + di*64 + hh*16;
    const float4* qp = (const float4*)(qkv + base);
    const float4 q0 = qp[0], q1 = qp[1], q2 = qp[2], q3 = qp[3];

    float s[9];
    bool  inb[9];
    int   noff[9];
    #pragma unroll
    for (int kk = 0; kk < 9; kk++) {
        const int dy = (kk/3 - 1) * r;
        const int dx = (kk%3 - 1) * r;
        const int ny = y + dy, nx = x + dx;
        const bool ok = (ny >= 0) & (ny < H_) & (nx >= 0) & (nx < W_);
        inb[kk]  = ok;
        noff[kk] = dy*W_ + dx;
        float sc = 0.f;
        if (ok) {
            const float4* kp = (const float4*)(qkv + base + (ptrdiff_t)noff[kk]*384 + 128);
            const float4 k0 = kp[0], k1 = kp[1], k2 = kp[2], k3 = kp[3];
            sc = q0.x*k0.x + q0.y*k0.y + q0.z*k0.z + q0.w*k0.w
               + q1.x*k1.x + q1.y*k1.y + q1.z*k1.z + q1.w*k1.w
               + q2.x*k2.x + q2.y*k2.y + q2.z*k2.z + q2.w*k2.w
               + q3.x*k3.x + q3.y*k3.y + q3.z*k3.z + q3.w*k3.w;
            sc *= 0.25f;  // hd^-0.5, hd=16
        }
        s[kk] = sc;
    }

    float mx = s[0];
    #pragma unroll
    for (int kk = 1; kk < 9; kk++) mx = fmaxf(mx, s[kk]);
    float sum = 0.f;
    #pragma unroll
    for (int kk = 0; kk < 9; kk++) { s[kk] = expf(s[kk] - mx); sum += s[kk]; }
    const float inv = 1.f / sum;

    float4 o0 = {0,0,0,0}, o1 = {0,0,0,0}, o2 = {0,0,0,0}, o3 = {0,0,0,0};
    #pragma unroll
    for (int kk = 0; kk < 9; kk++) {
        if (inb[kk]) {
            const float w = s[kk] * inv;
            const float4* vp = (const float4*)(qkv + base + (ptrdiff_t)noff[kk]*384 + 256);
            const float4 v0 = vp[0], v1 = vp[1], v2 = vp[2], v3 = vp[3];
            o0.x += w*v0.x; o0.y += w*v0.y; o0.z += w*v0.z; o0.w += w*v0.w;
            o1.x += w*v1.x; o1.y += w*v1.y; o1.z += w*v1.z; o1.w += w*v1.w;
            o2.x += w*v2.x; o2.y += w*v2.y; o2.z += w*v2.z; o2.w += w*v2.w;
            o3.x += w*v3.x; o3.y += w*v3.y; o3.z += w*v3.z; o3.w += w*v3.w;
        }
    }

    float4* op = (float4*)(att + (size_t)m * 128 + di*64 + hh*16);
    op[0] = o0; op[1] = o1; op[2] = o2; op[3] = o3;
}

// ---------------------------------------------------------------------------
extern "C" void kernel_launch(void* const* d_in, const int* in_sizes, int n_in,
                              void* d_out, int out_size)
{
    const float* x      = (const float*)d_in[0];
    const float* qkv_w  = (const float*)d_in[1];
    const float* proj_w = (const float*)d_in[2];
    const float* proj_b = (const float*)d_in[3];
    float* out = (float*)d_out;

    float *qkvbuf = nullptr, *attbuf = nullptr;
    cudaGetSymbolAddress((void**)&qkvbuf, g_qkv);
    cudaGetSymbolAddress((void**)&attbuf, g_att);

    // 1) QKV projection: [51200,128] x [384,128]^T -> [51200,384]
    dim3 g1(NPIX / 128, 384 / 128);
    tgemm_nt<<<g1, 256>>>(x, qkv_w, nullptr, qkvbuf, NPIX, 384, C_);

    // 2) Dilated neighborhood attention -> [51200,128]
    attn_kernel<<<(NPIX * 8) / 256, 256>>>(qkvbuf, attbuf);

    // 3) Output projection + bias: [51200,128] x [128,128]^T -> [51200,128]
    dim3 g3(NPIX / 128, 128 / 128);
    tgemm_nt<<<g3, 256>>>(attbuf, proj_w, proj_b, out, NPIX, 128, C_);
}

// round 3
// speedup vs baseline: 1.9822x; 1.1732x over previous
#include <cuda_runtime.h>
#include <math.h>
#include <stdint.h>

// Problem constants (BEVNet_26491358282245): x[2,160,160,128], qkv_w[384,128],
// proj_w[128,128], proj_b[128]. DILS=(1,2), KS=3, NH=8 -> hd=16, 4 heads/dilation.
#define B_ 2
#define H_ 160
#define W_ 160
#define C_ 128
#define NPIX (B_*H_*W_)   /* 51200 */

// Scratch (module-load allocated; no runtime alloc).
__device__ float g_qkv[(size_t)NPIX * 384];   // [pix, 3*C]  (q|k|v, each dil*64+head*16+c)
__device__ float g_att[(size_t)NPIX * 128];   // [pix, C] attention output (concat layout)

// ---------------------------------------------------------------------------
// tf32 tensor-core GEMM with cp.async double buffering.
// C[M,N] = A[M,K=128] * Bw[N,K=128]^T (+ bias[N])
// BM=BN=128, BK=16, 2 stages, 256 threads (8 warps 4x2), warp tile 32x64.
// ---------------------------------------------------------------------------
#define SMP 20   // smem row stride (floats): conflict-free fragment loads

__device__ __forceinline__ uint32_t f2tf32(float f) {
    uint32_t r;
    asm("cvt.rna.tf32.f32 %0, %1;" : "=r"(r) : "f"(f));
    return r;
}

__device__ __forceinline__ void mma_tf32(
    float& c0, float& c1, float& c2, float& c3,
    uint32_t a0, uint32_t a1, uint32_t a2, uint32_t a3,
    uint32_t b0, uint32_t b1)
{
    asm volatile(
        "mma.sync.aligned.m16n8k8.row.col.f32.tf32.tf32.f32 "
        "{%0,%1,%2,%3}, {%4,%5,%6,%7}, {%8,%9}, {%0,%1,%2,%3};"
        : "+f"(c0), "+f"(c1), "+f"(c2), "+f"(c3)
        : "r"(a0), "r"(a1), "r"(a2), "r"(a3), "r"(b0), "r"(b1));
}

__device__ __forceinline__ void cp16(uint32_t smem_dst, const void* gptr) {
    asm volatile("cp.async.ca.shared.global [%0], [%1], 16;\n"
                 :: "r"(smem_dst), "l"(gptr));
}

__global__ __launch_bounds__(256) void tgemm_ca(
    const float* __restrict__ A,
    const float* __restrict__ Bw,
    const float* __restrict__ bias,
    float* __restrict__ C,
    int M, int N)
{
    constexpr int K = 128;
    __shared__ float As[2][128 * SMP];
    __shared__ float Bs[2][128 * SMP];

    const int bm   = blockIdx.x * 128;
    const int bn   = blockIdx.y * 128;
    const int tid  = threadIdx.x;
    const int wid  = tid >> 5;
    const int lane = tid & 31;
    const int wm   = (wid & 3) * 32;
    const int wn   = (wid >> 2) * 64;
    const int grp  = lane >> 2;
    const int tg   = lane & 3;

    // Loader: row = tid>>1 (0..127), 8 floats per thread (two 16B cp.async).
    const int lr = tid >> 1;
    const int lc = (tid & 1) * 8;

    const float* Ag = A  + (size_t)(bm + lr) * K + lc;
    const float* Bg = Bw + (size_t)(bn + lr) * K + lc;
    const uint32_t sa0 = (uint32_t)__cvta_generic_to_shared(&As[0][lr * SMP + lc]);
    const uint32_t sb0 = (uint32_t)__cvta_generic_to_shared(&Bs[0][lr * SMP + lc]);
    const uint32_t stageA = (uint32_t)((char*)&As[1][0] - (char*)&As[0][0]);
    const uint32_t stageB = (uint32_t)((char*)&Bs[1][0] - (char*)&Bs[0][0]);

    float acc[2][8][4];
    #pragma unroll
    for (int i = 0; i < 2; i++)
        #pragma unroll
        for (int j = 0; j < 8; j++)
            #pragma unroll
            for (int q = 0; q < 4; q++) acc[i][j][q] = 0.f;

    // Preload stage 0.
    cp16(sa0,      Ag);     cp16(sa0 + 16, Ag + 4);
    cp16(sb0,      Bg);     cp16(sb0 + 16, Bg + 4);
    asm volatile("cp.async.commit_group;\n" ::: "memory");

    #pragma unroll
    for (int t = 0; t < 8; t++) {
        // Issue next stage (if any), then always commit (empty group ok).
        if (t < 7) {
            const int k0 = (t + 1) * 16;
            const uint32_t st = ((t + 1) & 1);
            cp16(sa0 + st*stageA,      Ag + k0);
            cp16(sa0 + st*stageA + 16, Ag + k0 + 4);
            cp16(sb0 + st*stageB,      Bg + k0);
            cp16(sb0 + st*stageB + 16, Bg + k0 + 4);
        }
        asm volatile("cp.async.commit_group;\n" ::: "memory");
        asm volatile("cp.async.wait_group 1;\n" ::: "memory");
        __syncthreads();

        const float* as = As[t & 1];
        const float* bs = Bs[t & 1];

        #pragma unroll
        for (int ks = 0; ks < 2; ks++) {
            const int kk = ks * 8;
            uint32_t afr[2][4];
            #pragma unroll
            for (int i = 0; i < 2; i++) {
                const int rb = wm + i * 16;
                afr[i][0] = f2tf32(as[(rb + grp)     * SMP + kk + tg]);
                afr[i][1] = f2tf32(as[(rb + grp + 8) * SMP + kk + tg]);
                afr[i][2] = f2tf32(as[(rb + grp)     * SMP + kk + tg + 4]);
                afr[i][3] = f2tf32(as[(rb + grp + 8) * SMP + kk + tg + 4]);
            }
            uint32_t bfr[8][2];
            #pragma unroll
            for (int j = 0; j < 8; j++) {
                const int cb = wn + j * 8;
                bfr[j][0] = f2tf32(bs[(cb + grp) * SMP + kk + tg]);
                bfr[j][1] = f2tf32(bs[(cb + grp) * SMP + kk + tg + 4]);
            }
            #pragma unroll
            for (int i = 0; i < 2; i++)
                #pragma unroll
                for (int j = 0; j < 8; j++)
                    mma_tf32(acc[i][j][0], acc[i][j][1], acc[i][j][2], acc[i][j][3],
                             afr[i][0], afr[i][1], afr[i][2], afr[i][3],
                             bfr[j][0], bfr[j][1]);
        }
        __syncthreads();
    }

    // Epilogue: c0/c1 contiguous along N -> float2 stores (+bias).
    #pragma unroll
    for (int j = 0; j < 8; j++) {
        const int col = bn + wn + j * 8 + 2 * tg;
        float b0 = bias ? bias[col]     : 0.f;
        float b1 = bias ? bias[col + 1] : 0.f;
        #pragma unroll
        for (int i = 0; i < 2; i++) {
            const int r0 = bm + wm + i * 16 + grp;
            float2 v0 = make_float2(acc[i][j][0] + b0, acc[i][j][1] + b1);
            float2 v1 = make_float2(acc[i][j][2] + b0, acc[i][j][3] + b1);
            *(float2*)(C + (size_t)r0 * N + col)       = v0;
            *(float2*)(C + (size_t)(r0 + 8) * N + col) = v1;
        }
    }
}

// ---------------------------------------------------------------------------
// Dilated 3x3 neighborhood attention, smem-tiled.
// Block = 16x16 pixel tile x one (dilation, head). 256 threads, 1 px each.
// Phase 1: K halo tile in smem (zero-filled OOB == reference zero padding),
// scores + softmax. Phase 2: reuse smem for V tile, accumulate output.
// Padded row stride 20 floats -> conflict-free LDS.128.
// ---------------------------------------------------------------------------
template<int R>
__global__ __launch_bounds__(256) void attn_tile(
    const float* __restrict__ qkv, float* __restrict__ att)
{
    constexpr int TW = 16 + 2 * R;
    constexpr int NR = TW * TW;
    __shared__ float sm[NR * 20];

    const int tile = blockIdx.x;          // 0..99
    const int b    = blockIdx.y;          // 0..1
    const int hh   = blockIdx.z;          // 0..3
    const int di   = (R == 1) ? 0 : 1;
    const int tx0  = (tile % 10) * 16;
    const int ty0  = (tile / 10) * 16;
    const int tid  = threadIdx.x;
    const int lx   = tid & 15;
    const int ly   = tid >> 4;
    const int off  = di * 64 + hh * 16;   // channel offset within q/k/v segment

    // Load q (registers).
    const size_t pix = ((size_t)b * H_ + (ty0 + ly)) * W_ + (tx0 + lx);
    const float4* qp = (const float4*)(qkv + pix * 384 + off);
    const float4 q0 = qp[0], q1 = qp[1], q2 = qp[2], q3 = qp[3];

    // Phase 1: K halo tile -> smem (zero fill OOB).
    #pragma unroll 4
    for (int i = tid; i < NR * 4; i += 256) {
        const int row = i >> 2, qd = i & 3;
        const int lyy = row / TW, lxx = row - lyy * TW;
        const int yy = ty0 + lyy - R, xx = tx0 + lxx - R;
        float4 v = make_float4(0.f, 0.f, 0.f, 0.f);
        if (yy >= 0 && yy < H_ && xx >= 0 && xx < W_)
            v = *(const float4*)(qkv + (((size_t)b * H_ + yy) * W_ + xx) * 384
                                 + 128 + off + qd * 4);
        *(float4*)&sm[row * 20 + qd * 4] = v;
    }
    __syncthreads();

    float s[9];
    #pragma unroll
    for (int ky = 0; ky < 3; ky++)
        #pragma unroll
        for (int kx = 0; kx < 3; kx++) {
            const float* kp = &sm[((ly + ky * R) * TW + (lx + kx * R)) * 20];
            const float4 k0 = *(const float4*)(kp);
            const float4 k1 = *(const float4*)(kp + 4);
            const float4 k2 = *(const float4*)(kp + 8);
            const float4 k3 = *(const float4*)(kp + 12);
            float sc = q0.x*k0.x + q0.y*k0.y + q0.z*k0.z + q0.w*k0.w
                     + q1.x*k1.x + q1.y*k1.y + q1.z*k1.z + q1.w*k1.w
                     + q2.x*k2.x + q2.y*k2.y + q2.z*k2.z + q2.w*k2.w
                     + q3.x*k3.x + q3.y*k3.y + q3.z*k3.z + q3.w*k3.w;
            s[ky * 3 + kx] = sc * 0.25f;   // hd^-0.5, hd=16
        }

    float mx = s[0];
    #pragma unroll
    for (int kk = 1; kk < 9; kk++) mx = fmaxf(mx, s[kk]);
    float sum = 0.f;
    #pragma unroll
    for (int kk = 0; kk < 9; kk++) { s[kk] = __expf(s[kk] - mx); sum += s[kk]; }
    const float inv = 1.f / sum;
    #pragma unroll
    for (int kk = 0; kk < 9; kk++) s[kk] *= inv;

    __syncthreads();   // done reading K tile

    // Phase 2: V halo tile -> same smem.
    #pragma unroll 4
    for (int i = tid; i < NR * 4; i += 256) {
        const int row = i >> 2, qd = i & 3;
        const int lyy = row / TW, lxx = row - lyy * TW;
        const int yy = ty0 + lyy - R, xx = tx0 + lxx - R;
        float4 v = make_float4(0.f, 0.f, 0.f, 0.f);
        if (yy >= 0 && yy < H_ && xx >= 0 && xx < W_)
            v = *(const float4*)(qkv + (((size_t)b * H_ + yy) * W_ + xx) * 384
                                 + 256 + off + qd * 4);
        *(float4*)&sm[row * 20 + qd * 4] = v;
    }
    __syncthreads();

    float4 o0 = {0,0,0,0}, o1 = {0,0,0,0}, o2 = {0,0,0,0}, o3 = {0,0,0,0};
    #pragma unroll
    for (int ky = 0; ky < 3; ky++)
        #pragma unroll
        for (int kx = 0; kx < 3; kx++) {
            const float w = s[ky * 3 + kx];
            const float* vp = &sm[((ly + ky * R) * TW + (lx + kx * R)) * 20];
            const float4 v0 = *(const float4*)(vp);
            const float4 v1 = *(const float4*)(vp + 4);
            const float4 v2 = *(const float4*)(vp + 8);
            const float4 v3 = *(const float4*)(vp + 12);
            o0.x += w*v0.x; o0.y += w*v0.y; o0.z += w*v0.z; o0.w += w*v0.w;
            o1.x += w*v1.x; o1.y += w*v1.y; o1.z += w*v1.z; o1.w += w*v1.w;
            o2.x += w*v2.x; o2.y += w*v2.y; o2.z += w*v2.z; o2.w += w*v2.w;
            o3.x += w*v3.x; o3.y += w*v3.y; o3.z += w*v3.z; o3.w += w*v3.w;
        }

    float4* op = (float4*)(att + pix * 128 + off);
    op[0] = o0; op[1] = o1; op[2] = o2; op[3] = o3;
}

// ---------------------------------------------------------------------------
extern "C" void kernel_launch(void* const* d_in, const int* in_sizes, int n_in,
                              void* d_out, int out_size)
{
    const float* x      = (const float*)d_in[0];
    const float* qkv_w  = (const float*)d_in[1];
    const float* proj_w = (const float*)d_in[2];
    const float* proj_b = (const float*)d_in[3];
    float* out = (float*)d_out;

    float *qkvbuf = nullptr, *attbuf = nullptr;
    cudaGetSymbolAddress((void**)&qkvbuf, g_qkv);
    cudaGetSymbolAddress((void**)&attbuf, g_att);

    // 1) QKV projection: [51200,128] x [384,128]^T -> [51200,384]
    dim3 g1(NPIX / 128, 384 / 128);
    tgemm_ca<<<g1, 256>>>(x, qkv_w, nullptr, qkvbuf, NPIX, 384);

    // 2) Dilated neighborhood attention -> [51200,128]
    dim3 ga(100, 2, 4);
    attn_tile<1><<<ga, 256>>>(qkvbuf, attbuf);
    attn_tile<2><<<ga, 256>>>(qkvbuf, attbuf);

    // 3) Output projection + bias: [51200,128] x [128,128]^T -> [51200,128]
    dim3 g3(NPIX / 128, 128 / 128);
    tgemm_ca<<<g3, 256>>>(attbuf, proj_w, proj_b, out, NPIX, 128);
}